// round 12
// baseline (speedup 1.0000x reference)
#include <cuda_runtime.h>
#include <cstdint>

// ---------------------------------------------------------------------------
// GraphSAGE, 3 layers: h = SAGE(h) -> LN -> ReLU (x2), final SAGE (no LN).
// SAGE(h) = h @ ws + (segsum(h[src]->dst)/deg) @ wn + b
//         = h @ ws + segsum((h@wn)[src]->dst)/deg + b      (linearity)
// Pipeline per layer:
//   GEMM  self = h @ ws + b        (N x dout)
//   GEMM  hn   = h @ wn            (N x dout)
//   fused agg+epilogue: per dst node gather hn rows via CSR, /deg, +self,
//                       LayerNorm+ReLU (layers 0,1) or raw (layer 2).
// CSR (dst -> list of src) is rebuilt every call with int atomics + scan:
// no float atomics anywhere.
// ---------------------------------------------------------------------------

#define NN 50000
#define EMAX 800000
#define KDIM 256

__device__ float g_self[(size_t)NN * 256];
__device__ float g_hn[(size_t)NN * 256];
__device__ float g_h[(size_t)NN * 256];

__device__ int g_cnt[NN];        // counts, then reused as fill cursor
__device__ int g_off[NN + 1];    // CSR row offsets
__device__ int g_bsum[256];      // scan block sums
__device__ int g_csr[EMAX];      // CSR src indices

// ------------------------------ CSR build ---------------------------------

__global__ void k_zero(int n) {
    int i = blockIdx.x * 256 + threadIdx.x;
    if (i < n) g_cnt[i] = 0;
}

__global__ void k_count(const int* __restrict__ dst, int E) {
    int e = blockIdx.x * 256 + threadIdx.x;
    if (e < E) atomicAdd(&g_cnt[dst[e]], 1);
}

__global__ void k_scan_chunk(int n) {
    __shared__ int s[256];
    int tid = threadIdx.x;
    int i = blockIdx.x * 256 + tid;
    int v = (i < n) ? g_cnt[i] : 0;
    s[tid] = v;
    __syncthreads();
#pragma unroll
    for (int d = 1; d < 256; d <<= 1) {
        int t = (tid >= d) ? s[tid - d] : 0;
        __syncthreads();
        s[tid] += t;
        __syncthreads();
    }
    if (i < n) g_off[i + 1] = s[tid];          // partial inclusive
    if (tid == 255) g_bsum[blockIdx.x] = s[255];
}

__global__ void k_scan_top(int nb) {
    __shared__ int s[256];
    int tid = threadIdx.x;
    int v = (tid < nb) ? g_bsum[tid] : 0;
    s[tid] = v;
    __syncthreads();
#pragma unroll
    for (int d = 1; d < 256; d <<= 1) {
        int t = (tid >= d) ? s[tid - d] : 0;
        __syncthreads();
        s[tid] += t;
        __syncthreads();
    }
    if (tid < nb) g_bsum[tid] = s[tid] - v;    // exclusive
}

__global__ void k_scan_add(int n) {
    int i = blockIdx.x * 256 + threadIdx.x;
    if (i < n) g_off[i + 1] += g_bsum[blockIdx.x];
    if (i == 0) g_off[0] = 0;
}

__global__ void k_cursor(int n) {
    int i = blockIdx.x * 256 + threadIdx.x;
    if (i < n) g_cnt[i] = g_off[i];
}

__global__ void k_fill(const int* __restrict__ src, const int* __restrict__ dst, int E) {
    int e = blockIdx.x * 256 + threadIdx.x;
    if (e < E) {
        int d = dst[e];
        int p = atomicAdd(&g_cnt[d], 1);
        g_csr[p] = src[e];
    }
}

// -------------------------------- SGEMM -----------------------------------
// C[N x dout] = A[N x 256] @ W[256 x dout] (+ bias).  Tiles: BM=128 BN=64
// BK=16, 256 threads, 8x4 per-thread microtile. out_sel: 0 -> g_self,
// 1 -> g_hn.  use_gh: 0 -> A = Aext (layer-0 feat), 1 -> A = g_h.

__global__ void __launch_bounds__(256) k_gemm(
    const float* __restrict__ Aext, int use_gh,
    const float* __restrict__ W, const float* __restrict__ bias,
    int out_sel, int N, int dout)
{
    const float* A = use_gh ? (const float*)g_h : Aext;
    float* C = out_sel ? g_hn : g_self;

    __shared__ __align__(16) float As[16][128];
    __shared__ __align__(16) float Bs[16][64];

    const int tid = threadIdx.x;
    const int tx = tid & 15;        // 0..15, 4 cols each
    const int ty = tid >> 4;        // 0..15, 8 rows each
    const int rowBase = blockIdx.y * 128;
    const int colBase = blockIdx.x * 64;

    float acc[8][4];
#pragma unroll
    for (int r = 0; r < 8; ++r)
#pragma unroll
        for (int c = 0; c < 4; ++c) acc[r][c] = 0.f;

    // A tile loader mapping: thread -> (row ar, k-half ah)
    const int ar = tid >> 1;            // 0..127
    const int ah = (tid & 1) << 3;      // 0 or 8
    const bool a_ok = (rowBase + ar) < N;
    const float* Ap = A + (size_t)(rowBase + ar) * KDIM + ah;

    // B tile loader mapping: thread -> (k row bk, col group bn)
    const int bk = tid >> 4;            // 0..15
    const int bn = (tid & 15) << 2;     // 0..60
    const float* Wp = W + (size_t)bk * dout + colBase + bn;

    for (int kt = 0; kt < KDIM; kt += 16) {
        float4 a0 = make_float4(0.f, 0.f, 0.f, 0.f);
        float4 a1 = a0;
        if (a_ok) {
            a0 = *(const float4*)(Ap + kt);
            a1 = *(const float4*)(Ap + kt + 4);
        }
        As[ah + 0][ar] = a0.x; As[ah + 1][ar] = a0.y;
        As[ah + 2][ar] = a0.z; As[ah + 3][ar] = a0.w;
        As[ah + 4][ar] = a1.x; As[ah + 5][ar] = a1.y;
        As[ah + 6][ar] = a1.z; As[ah + 7][ar] = a1.w;

        float4 bv = *(const float4*)(Wp + (size_t)kt * dout);
        *(float4*)&Bs[bk][bn] = bv;
        __syncthreads();

#pragma unroll
        for (int k = 0; k < 16; ++k) {
            const float4 fa0 = *(const float4*)&As[k][ty * 8];
            const float4 fa1 = *(const float4*)&As[k][ty * 8 + 4];
            const float4 fb  = *(const float4*)&Bs[k][tx * 4];
            const float av[8] = {fa0.x, fa0.y, fa0.z, fa0.w,
                                 fa1.x, fa1.y, fa1.z, fa1.w};
            const float bw[4] = {fb.x, fb.y, fb.z, fb.w};
#pragma unroll
            for (int r = 0; r < 8; ++r)
#pragma unroll
                for (int c = 0; c < 4; ++c)
                    acc[r][c] = fmaf(av[r], bw[c], acc[r][c]);
        }
        __syncthreads();
    }

    float badd[4] = {0.f, 0.f, 0.f, 0.f};
    if (bias) {
#pragma unroll
        for (int c = 0; c < 4; ++c) badd[c] = bias[colBase + tx * 4 + c];
    }
#pragma unroll
    for (int r = 0; r < 8; ++r) {
        int row = rowBase + ty * 8 + r;
        if (row < N) {
            float4 o;
            o.x = acc[r][0] + badd[0];
            o.y = acc[r][1] + badd[1];
            o.z = acc[r][2] + badd[2];
            o.w = acc[r][3] + badd[3];
            *(float4*)&C[(size_t)row * dout + colBase + tx * 4] = o;
        }
    }
}

// -------------------- fused aggregate + epilogue ---------------------------

__device__ __forceinline__ void block_reduce2(float& a, float& b, int tid) {
#pragma unroll
    for (int o = 16; o > 0; o >>= 1) {
        a += __shfl_xor_sync(0xffffffffu, a, o);
        b += __shfl_xor_sync(0xffffffffu, b, o);
    }
    __shared__ float sa[8], sb[8];
    const int w = tid >> 5, l = tid & 31;
    if (l == 0) { sa[w] = a; sb[w] = b; }
    __syncthreads();
    if (w == 0) {
        float ra = (l < 8) ? sa[l] : 0.f;
        float rb = (l < 8) ? sb[l] : 0.f;
#pragma unroll
        for (int o = 4; o > 0; o >>= 1) {
            ra += __shfl_xor_sync(0xffffffffu, ra, o);
            rb += __shfl_xor_sync(0xffffffffu, rb, o);
        }
        if (l == 0) { sa[0] = ra; sb[0] = rb; }
    }
    __syncthreads();
    a = sa[0];
    b = sb[0];
}

// layers 0,1: dout=256, LN + ReLU, writes g_h
__global__ void __launch_bounds__(256) k_agg_ln(
    const float* __restrict__ deg, const float* __restrict__ g,
    const float* __restrict__ be)
{
    const int i = blockIdx.x;
    const int c = threadIdx.x;
    const int s = g_off[i], e2 = g_off[i + 1];
    float acc = 0.f;
    int e = s;
    for (; e + 4 <= e2; e += 4) {
        const int i0 = g_csr[e + 0];
        const int i1 = g_csr[e + 1];
        const int i2 = g_csr[e + 2];
        const int i3 = g_csr[e + 3];
        float v0 = __ldg(&g_hn[(size_t)i0 * 256 + c]);
        float v1 = __ldg(&g_hn[(size_t)i1 * 256 + c]);
        float v2 = __ldg(&g_hn[(size_t)i2 * 256 + c]);
        float v3 = __ldg(&g_hn[(size_t)i3 * 256 + c]);
        acc += (v0 + v1) + (v2 + v3);
    }
    for (; e < e2; ++e) acc += __ldg(&g_hn[(size_t)g_csr[e] * 256 + c]);

    float val = g_self[(size_t)i * 256 + c] + acc / deg[i];

    float sum = val, sq = val * val;
    block_reduce2(sum, sq, c);
    const float mean = sum * (1.f / 256.f);
    const float var = sq * (1.f / 256.f) - mean * mean;
    const float rstd = rsqrtf(var + 1e-5f);
    float o = (val - mean) * rstd * g[c] + be[c];
    g_h[(size_t)i * 256 + c] = fmaxf(o, 0.f);
}

// layer 2: dout=128, no LN, writes d_out
__global__ void __launch_bounds__(128) k_agg_final(
    const float* __restrict__ deg, float* __restrict__ out)
{
    const int i = blockIdx.x;
    const int c = threadIdx.x;
    const int s = g_off[i], e2 = g_off[i + 1];
    float acc = 0.f;
    int e = s;
    for (; e + 4 <= e2; e += 4) {
        const int i0 = g_csr[e + 0];
        const int i1 = g_csr[e + 1];
        const int i2 = g_csr[e + 2];
        const int i3 = g_csr[e + 3];
        acc += __ldg(&g_hn[(size_t)i0 * 128 + c])
             + __ldg(&g_hn[(size_t)i1 * 128 + c])
             + __ldg(&g_hn[(size_t)i2 * 128 + c])
             + __ldg(&g_hn[(size_t)i3 * 128 + c]);
    }
    for (; e < e2; ++e) acc += __ldg(&g_hn[(size_t)g_csr[e] * 128 + c]);

    out[(size_t)i * 128 + c] = g_self[(size_t)i * 128 + c] + acc / deg[i];
}

// ------------------------------- launcher ----------------------------------

extern "C" void kernel_launch(void* const* d_in, const int* in_sizes, int n_in,
                              void* d_out, int out_size)
{
    const float* feat   = (const float*)d_in[0];
    const int*   ei     = (const int*)  d_in[1];
    const float* in_deg = (const float*)d_in[2];
    const float* ws0 = (const float*)d_in[3];
    const float* wn0 = (const float*)d_in[4];
    const float* b0  = (const float*)d_in[5];
    const float* ws1 = (const float*)d_in[6];
    const float* wn1 = (const float*)d_in[7];
    const float* b1  = (const float*)d_in[8];
    const float* ws2 = (const float*)d_in[9];
    const float* wn2 = (const float*)d_in[10];
    const float* b2  = (const float*)d_in[11];
    const float* g0  = (const float*)d_in[12];
    const float* be0 = (const float*)d_in[13];
    const float* g1  = (const float*)d_in[14];
    const float* be1 = (const float*)d_in[15];

    const int N = in_sizes[0] / 256;   // 50000
    const int E = in_sizes[1] / 2;     // 800000
    const int* src = ei;
    const int* dst = ei + E;
    float* out = (float*)d_out;

    const int nbN = (N + 255) / 256;   // 196 (<= 256 required for scan_top)
    const int nbE = (E + 255) / 256;

    // ---- CSR build (dst -> srcs), int atomics only ----
    k_zero<<<nbN, 256>>>(N);
    k_count<<<nbE, 256>>>(dst, E);
    k_scan_chunk<<<nbN, 256>>>(N);
    k_scan_top<<<1, 256>>>(nbN);
    k_scan_add<<<nbN, 256>>>(N);
    k_cursor<<<nbN, 256>>>(N);
    k_fill<<<nbE, 256>>>(src, dst, E);

    const int rowBlocks = (N + 127) / 128;

    // ---- layer 0: input = feat (dout 256) ----
    k_gemm<<<dim3(4, rowBlocks), 256>>>(feat, 0, ws0, b0, 0, N, 256);
    k_gemm<<<dim3(4, rowBlocks), 256>>>(feat, 0, wn0, nullptr, 1, N, 256);
    k_agg_ln<<<N, 256>>>(in_deg, g0, be0);

    // ---- layer 1: input = g_h (dout 256) ----
    k_gemm<<<dim3(4, rowBlocks), 256>>>(feat, 1, ws1, b1, 0, N, 256);
    k_gemm<<<dim3(4, rowBlocks), 256>>>(feat, 1, wn1, nullptr, 1, N, 256);
    k_agg_ln<<<N, 256>>>(in_deg, g1, be1);

    // ---- layer 2: input = g_h (dout 128, no LN) ----
    k_gemm<<<dim3(2, rowBlocks), 256>>>(feat, 1, ws2, b2, 0, N, 128);
    k_gemm<<<dim3(2, rowBlocks), 256>>>(feat, 1, wn2, nullptr, 1, N, 128);
    k_agg_final<<<N, 128>>>(in_deg, out);
}

// round 13
// speedup vs baseline: 1.5648x; 1.5648x over previous
#include <cuda_runtime.h>
#include <cstdint>

// ---------------------------------------------------------------------------
// GraphSAGE, 3 layers. SAGE(h) = h@ws + segsum((h@wn)[src]->dst)/deg + b.
// R12: GEMMs moved to tf32 tensor cores (mma.sync m16n8k8), fp32 accumulate.
// Pipeline per layer: 2 tf32 GEMMs -> fused CSR-gather + LN + ReLU epilogue.
// CSR rebuilt per call with int atomics + scan (no float atomics).
// ---------------------------------------------------------------------------

#define NN 50000
#define EMAX 800000
#define KDIM 256

__device__ float g_self[(size_t)NN * 256];
__device__ float g_hn[(size_t)NN * 256];
__device__ float g_h[(size_t)NN * 256];

__device__ int g_cnt[NN];
__device__ int g_off[NN + 1];
__device__ int g_bsum[256];
__device__ int g_csr[EMAX];

// ------------------------------ CSR build ---------------------------------

__global__ void k_zero(int n) {
    int i = blockIdx.x * 256 + threadIdx.x;
    if (i < n) g_cnt[i] = 0;
}

__global__ void k_count(const int* __restrict__ dst, int E) {
    int e = blockIdx.x * 256 + threadIdx.x;
    if (e < E) atomicAdd(&g_cnt[dst[e]], 1);
}

__global__ void k_scan_chunk(int n) {
    __shared__ int s[256];
    int tid = threadIdx.x;
    int i = blockIdx.x * 256 + tid;
    int v = (i < n) ? g_cnt[i] : 0;
    s[tid] = v;
    __syncthreads();
#pragma unroll
    for (int d = 1; d < 256; d <<= 1) {
        int t = (tid >= d) ? s[tid - d] : 0;
        __syncthreads();
        s[tid] += t;
        __syncthreads();
    }
    if (i < n) g_off[i + 1] = s[tid];
    if (tid == 255) g_bsum[blockIdx.x] = s[255];
}

__global__ void k_scan_top(int nb) {
    __shared__ int s[256];
    int tid = threadIdx.x;
    int v = (tid < nb) ? g_bsum[tid] : 0;
    s[tid] = v;
    __syncthreads();
#pragma unroll
    for (int d = 1; d < 256; d <<= 1) {
        int t = (tid >= d) ? s[tid - d] : 0;
        __syncthreads();
        s[tid] += t;
        __syncthreads();
    }
    if (tid < nb) g_bsum[tid] = s[tid] - v;
}

__global__ void k_scan_add(int n) {
    int i = blockIdx.x * 256 + threadIdx.x;
    if (i < n) g_off[i + 1] += g_bsum[blockIdx.x];
    if (i == 0) g_off[0] = 0;
}

__global__ void k_cursor(int n) {
    int i = blockIdx.x * 256 + threadIdx.x;
    if (i < n) g_cnt[i] = g_off[i];
}

__global__ void k_fill(const int* __restrict__ src, const int* __restrict__ dst, int E) {
    int e = blockIdx.x * 256 + threadIdx.x;
    if (e < E) {
        int d = dst[e];
        int p = atomicAdd(&g_cnt[d], 1);
        g_csr[p] = src[e];
    }
}

// --------------------------- tf32 tensor GEMM ------------------------------
// C[N x dout] = A[N x 256] @ W[256 x dout] (+bias).
// BM=128 BN=128 BK=16. 256 threads = 8 warps (2x4), warp tile 64x32.
// smem holds tf32 fragments in mma order with XOR swizzle; LDS conflict-free.

__device__ __forceinline__ uint32_t f2tf32(float v) {
    uint32_t r;
    asm("cvt.rna.tf32.f32 %0, %1;" : "=r"(r) : "f"(v));
    return r;
}

__device__ __forceinline__ void mma_tf32(float* c, const uint32_t* a, const uint32_t* b) {
    asm volatile(
        "mma.sync.aligned.m16n8k8.row.col.f32.tf32.tf32.f32 "
        "{%0,%1,%2,%3}, {%4,%5,%6,%7}, {%8,%9}, {%0,%1,%2,%3};"
        : "+f"(c[0]), "+f"(c[1]), "+f"(c[2]), "+f"(c[3])
        : "r"(a[0]), "r"(a[1]), "r"(a[2]), "r"(a[3]),
          "r"(b[0]), "r"(b[1]));
}

__device__ __forceinline__ int permu(int lane, int block) {
    return (lane ^ (lane >> 2) ^ block) & 31;
}

__global__ void __launch_bounds__(256) k_gemm_tc(
    const float* __restrict__ Aext, int use_gh,
    const float* __restrict__ W, const float* __restrict__ bias,
    int out_sel, int N, int dout)
{
    const float* A = use_gh ? (const float*)g_h : Aext;
    float* C = out_sel ? g_hn : g_self;

    // sA: block = kc*8+mt (16 blocks) * 32 lanes * 4 slots
    // sB: block = kc*16+nt (32 blocks) * 32 lanes * 2 slots
    __shared__ __align__(16) uint32_t sA[2048];
    __shared__ __align__(16) uint32_t sB[2048];

    const int tid  = threadIdx.x;
    const int lane = tid & 31;
    const int w    = tid >> 5;
    const int wr   = w >> 2;     // 0..1
    const int wc   = w & 3;      // 0..3
    const int rowBase = blockIdx.y * 128;
    const int colBase = blockIdx.x * 128;

    float acc[4][4][4];
#pragma unroll
    for (int mt = 0; mt < 4; ++mt)
#pragma unroll
        for (int nt = 0; nt < 4; ++nt)
#pragma unroll
            for (int s = 0; s < 4; ++s) acc[mt][nt][s] = 0.f;

    // A loader mapping: row ar (0..127), k-half via tid&1
    const int ar   = tid >> 1;
    const int akc  = tid & 1;                 // kc of this thread's 8 k's
    const int a_mt = ar >> 4;
    const int a_hf = (ar >> 3) & 1;           // half (row>=8 within m16)
    const int a_g  = ar & 7;
    const int a_blk = akc * 8 + a_mt;
    const bool a_ok = (rowBase + ar) < N;
    const float* Ap = A + (size_t)(rowBase + ar) * KDIM + akc * 8;

    // B loader mapping: k-rows r and r+8, 4 cols per row
    const int br = tid >> 5;                  // 0..7
    const int bc4 = tid & 31;                 // 0..31

    for (int kt = 0; kt < KDIM; kt += 16) {
        // ---- A scatter ----
        float4 v0 = make_float4(0.f, 0.f, 0.f, 0.f), v1 = v0;
        if (a_ok) {
            v0 = *(const float4*)(Ap + kt);
            v1 = *(const float4*)(Ap + kt + 4);
        }
        {
            uint32_t* base = &sA[a_blk * 128];
            const float e0[4] = {v0.x, v0.y, v0.z, v0.w};
            const float e1[4] = {v1.x, v1.y, v1.z, v1.w};
#pragma unroll
            for (int j = 0; j < 4; ++j) {
                int L = a_g * 4 + j;
                int p = permu(L, a_blk);
                base[p * 4 + a_hf]     = f2tf32(e0[j]);   // khalf=0: slot=half
                base[p * 4 + 2 + a_hf] = f2tf32(e1[j]);   // khalf=1: slot=2+half
            }
        }
        // ---- B scatter ----
#pragma unroll
        for (int rb = 0; rb < 2; ++rb) {
            const int rk = br + rb * 8;             // 0..15
            const float4 v = *(const float4*)&W[(size_t)(kt + rk) * dout + colBase + bc4 * 4];
            const int kc = rk >> 3;
            const int kq = rk & 7;
            const int khalf = kq >> 2;
            const int q = kq & 3;
            const float e[4] = {v.x, v.y, v.z, v.w};
#pragma unroll
            for (int j = 0; j < 4; ++j) {
                int n = bc4 * 4 + j;
                int blk = kc * 16 + (n >> 3);
                int L = (n & 7) * 4 + q;
                int p = permu(L, blk);
                sB[blk * 64 + p * 2 + khalf] = f2tf32(e[j]);
            }
        }
        __syncthreads();

        // ---- compute ----
#pragma unroll
        for (int kc = 0; kc < 2; ++kc) {
            uint32_t afr[4][4];
            uint32_t bfr[4][2];
#pragma unroll
            for (int mt = 0; mt < 4; ++mt) {
                int blk = kc * 8 + wr * 4 + mt;
                int p = permu(lane, blk);
                const uint4 v = *(const uint4*)&sA[blk * 128 + p * 4];
                afr[mt][0] = v.x; afr[mt][1] = v.y; afr[mt][2] = v.z; afr[mt][3] = v.w;
            }
#pragma unroll
            for (int nt = 0; nt < 4; ++nt) {
                int blk = kc * 16 + wc * 4 + nt;
                int p = permu(lane, blk);
                const uint2 v = *(const uint2*)&sB[blk * 64 + p * 2];
                bfr[nt][0] = v.x; bfr[nt][1] = v.y;
            }
#pragma unroll
            for (int mt = 0; mt < 4; ++mt)
#pragma unroll
                for (int nt = 0; nt < 4; ++nt)
                    mma_tf32(acc[mt][nt], afr[mt], bfr[nt]);
        }
        __syncthreads();
    }

    // ---- epilogue ----
    const int g = lane >> 2, q = lane & 3;
#pragma unroll
    for (int nt = 0; nt < 4; ++nt) {
        const int col = colBase + wc * 32 + nt * 8 + 2 * q;
        float bx = 0.f, by = 0.f;
        if (bias) {
            const float2 bb = *(const float2*)&bias[col];
            bx = bb.x; by = bb.y;
        }
#pragma unroll
        for (int mt = 0; mt < 4; ++mt) {
            const int row = rowBase + wr * 64 + mt * 16 + g;
            if (row < N) {
                float2 o = make_float2(acc[mt][nt][0] + bx, acc[mt][nt][1] + by);
                *(float2*)&C[(size_t)row * dout + col] = o;
            }
            if (row + 8 < N) {
                float2 o = make_float2(acc[mt][nt][2] + bx, acc[mt][nt][3] + by);
                *(float2*)&C[(size_t)(row + 8) * dout + col] = o;
            }
        }
    }
}

// -------------------- fused aggregate + epilogue ---------------------------

__device__ __forceinline__ void block_reduce2(float& a, float& b, int tid) {
#pragma unroll
    for (int o = 16; o > 0; o >>= 1) {
        a += __shfl_xor_sync(0xffffffffu, a, o);
        b += __shfl_xor_sync(0xffffffffu, b, o);
    }
    __shared__ float sa[8], sb[8];
    const int w = tid >> 5, l = tid & 31;
    if (l == 0) { sa[w] = a; sb[w] = b; }
    __syncthreads();
    if (w == 0) {
        float ra = (l < 8) ? sa[l] : 0.f;
        float rb = (l < 8) ? sb[l] : 0.f;
#pragma unroll
        for (int o = 4; o > 0; o >>= 1) {
            ra += __shfl_xor_sync(0xffffffffu, ra, o);
            rb += __shfl_xor_sync(0xffffffffu, rb, o);
        }
        if (l == 0) { sa[0] = ra; sb[0] = rb; }
    }
    __syncthreads();
    a = sa[0];
    b = sb[0];
}

__global__ void __launch_bounds__(256) k_agg_ln(
    const float* __restrict__ deg, const float* __restrict__ g,
    const float* __restrict__ be)
{
    const int i = blockIdx.x;
    const int c = threadIdx.x;
    const int s = g_off[i], e2 = g_off[i + 1];
    float acc = 0.f;
    int e = s;
    for (; e + 4 <= e2; e += 4) {
        const int i0 = g_csr[e + 0];
        const int i1 = g_csr[e + 1];
        const int i2 = g_csr[e + 2];
        const int i3 = g_csr[e + 3];
        float v0 = __ldg(&g_hn[(size_t)i0 * 256 + c]);
        float v1 = __ldg(&g_hn[(size_t)i1 * 256 + c]);
        float v2 = __ldg(&g_hn[(size_t)i2 * 256 + c]);
        float v3 = __ldg(&g_hn[(size_t)i3 * 256 + c]);
        acc += (v0 + v1) + (v2 + v3);
    }
    for (; e < e2; ++e) acc += __ldg(&g_hn[(size_t)g_csr[e] * 256 + c]);

    float val = g_self[(size_t)i * 256 + c] + acc / deg[i];

    float sum = val, sq = val * val;
    block_reduce2(sum, sq, c);
    const float mean = sum * (1.f / 256.f);
    const float var = sq * (1.f / 256.f) - mean * mean;
    const float rstd = rsqrtf(var + 1e-5f);
    float o = (val - mean) * rstd * g[c] + be[c];
    g_h[(size_t)i * 256 + c] = fmaxf(o, 0.f);
}

__global__ void __launch_bounds__(128) k_agg_final(
    const float* __restrict__ deg, float* __restrict__ out)
{
    const int i = blockIdx.x;
    const int c = threadIdx.x;
    const int s = g_off[i], e2 = g_off[i + 1];
    float acc = 0.f;
    int e = s;
    for (; e + 4 <= e2; e += 4) {
        const int i0 = g_csr[e + 0];
        const int i1 = g_csr[e + 1];
        const int i2 = g_csr[e + 2];
        const int i3 = g_csr[e + 3];
        acc += __ldg(&g_hn[(size_t)i0 * 128 + c])
             + __ldg(&g_hn[(size_t)i1 * 128 + c])
             + __ldg(&g_hn[(size_t)i2 * 128 + c])
             + __ldg(&g_hn[(size_t)i3 * 128 + c]);
    }
    for (; e < e2; ++e) acc += __ldg(&g_hn[(size_t)g_csr[e] * 128 + c]);

    out[(size_t)i * 128 + c] = g_self[(size_t)i * 128 + c] + acc / deg[i];
}

// ------------------------------- launcher ----------------------------------

extern "C" void kernel_launch(void* const* d_in, const int* in_sizes, int n_in,
                              void* d_out, int out_size)
{
    const float* feat   = (const float*)d_in[0];
    const int*   ei     = (const int*)  d_in[1];
    const float* in_deg = (const float*)d_in[2];
    const float* ws0 = (const float*)d_in[3];
    const float* wn0 = (const float*)d_in[4];
    const float* b0  = (const float*)d_in[5];
    const float* ws1 = (const float*)d_in[6];
    const float* wn1 = (const float*)d_in[7];
    const float* b1  = (const float*)d_in[8];
    const float* ws2 = (const float*)d_in[9];
    const float* wn2 = (const float*)d_in[10];
    const float* b2  = (const float*)d_in[11];
    const float* g0  = (const float*)d_in[12];
    const float* be0 = (const float*)d_in[13];
    const float* g1  = (const float*)d_in[14];
    const float* be1 = (const float*)d_in[15];

    const int N = in_sizes[0] / 256;   // 50000
    const int E = in_sizes[1] / 2;     // 800000
    const int* src = ei;
    const int* dst = ei + E;
    float* out = (float*)d_out;

    const int nbN = (N + 255) / 256;
    const int nbE = (E + 255) / 256;

    // ---- CSR build ----
    k_zero<<<nbN, 256>>>(N);
    k_count<<<nbE, 256>>>(dst, E);
    k_scan_chunk<<<nbN, 256>>>(N);
    k_scan_top<<<1, 256>>>(nbN);
    k_scan_add<<<nbN, 256>>>(N);
    k_cursor<<<nbN, 256>>>(N);
    k_fill<<<nbE, 256>>>(src, dst, E);

    const int rowBlocks = (N + 127) / 128;

    // ---- layer 0 (dout 256) ----
    k_gemm_tc<<<dim3(2, rowBlocks), 256>>>(feat, 0, ws0, b0, 0, N, 256);
    k_gemm_tc<<<dim3(2, rowBlocks), 256>>>(feat, 0, wn0, nullptr, 1, N, 256);
    k_agg_ln<<<N, 256>>>(in_deg, g0, be0);

    // ---- layer 1 (dout 256) ----
    k_gemm_tc<<<dim3(2, rowBlocks), 256>>>(feat, 1, ws1, b1, 0, N, 256);
    k_gemm_tc<<<dim3(2, rowBlocks), 256>>>(feat, 1, wn1, nullptr, 1, N, 256);
    k_agg_ln<<<N, 256>>>(in_deg, g1, be1);

    // ---- layer 2 (dout 128, no LN) ----
    k_gemm_tc<<<dim3(1, rowBlocks), 256>>>(feat, 1, ws2, b2, 0, N, 128);
    k_gemm_tc<<<dim3(1, rowBlocks), 256>>>(feat, 1, wn2, nullptr, 1, N, 128);
    k_agg_final<<<N, 128>>>(in_deg, out);
}

// round 14
// speedup vs baseline: 2.1716x; 1.3878x over previous
#include <cuda_runtime.h>
#include <cstdint>

// ---------------------------------------------------------------------------
// GraphSAGE, 3 layers. SAGE(h) = h@ws + segsum((h@wn)[src]->dst)/deg + b.
// R13: fused dual tf32 GEMM per layer (gridDim.z=2), register-staged pipeline,
// hoisted swizzle addressing, STS.64 A-scatter; float4 aggregation kernels.
// Launch order puts the layer-0 GEMM at launch #6 so ncu (-s 5) profiles it.
// ---------------------------------------------------------------------------

#define NN 50000
#define EMAX 800000
#define KDIM 256

__device__ float g_self[(size_t)NN * 256];
__device__ float g_hn[(size_t)NN * 256];
__device__ float g_h[(size_t)NN * 256];

__device__ int g_cnt[NN];
__device__ int g_off[NN + 1];
__device__ int g_bsum[256];
__device__ int g_csr[EMAX];

// ------------------------------ CSR build ---------------------------------

__global__ void k_zero(int n) {
    int i = blockIdx.x * 256 + threadIdx.x;
    if (i < n) g_cnt[i] = 0;
}

__global__ void k_count(const int* __restrict__ dst, int E) {
    int e = blockIdx.x * 256 + threadIdx.x;
    if (e < E) atomicAdd(&g_cnt[dst[e]], 1);
}

__global__ void k_scan_chunk(int n) {
    __shared__ int s[256];
    int tid = threadIdx.x;
    int i = blockIdx.x * 256 + tid;
    int v = (i < n) ? g_cnt[i] : 0;
    s[tid] = v;
    __syncthreads();
#pragma unroll
    for (int d = 1; d < 256; d <<= 1) {
        int t = (tid >= d) ? s[tid - d] : 0;
        __syncthreads();
        s[tid] += t;
        __syncthreads();
    }
    if (i < n) g_off[i + 1] = s[tid];
    if (tid == 255) g_bsum[blockIdx.x] = s[255];
}

__global__ void k_scan_top(int nb) {
    __shared__ int s[256];
    int tid = threadIdx.x;
    int v = (tid < nb) ? g_bsum[tid] : 0;
    s[tid] = v;
    __syncthreads();
#pragma unroll
    for (int d = 1; d < 256; d <<= 1) {
        int t = (tid >= d) ? s[tid - d] : 0;
        __syncthreads();
        s[tid] += t;
        __syncthreads();
    }
    if (tid < nb) g_bsum[tid] = s[tid] - v;
}

__global__ void k_scan_add(int n) {
    int i = blockIdx.x * 256 + threadIdx.x;
    if (i < n) g_off[i + 1] += g_bsum[blockIdx.x];
    if (i == 0) g_off[0] = 0;
}

__global__ void k_cursor(int n) {
    int i = blockIdx.x * 256 + threadIdx.x;
    if (i < n) g_cnt[i] = g_off[i];
}

__global__ void k_fill(const int* __restrict__ src, const int* __restrict__ dst, int E) {
    int e = blockIdx.x * 256 + threadIdx.x;
    if (e < E) {
        int d = dst[e];
        int p = atomicAdd(&g_cnt[d], 1);
        g_csr[p] = src[e];
    }
}

// --------------------------- tf32 tensor GEMM ------------------------------
// Fused pair: z=0 -> C=g_self (W=Wa, +bias), z=1 -> C=g_hn (W=Wb).
// BM=128 BN=128 BK=16. 256 threads, 8 warps (2x4), warp tile 64x32.
// Register-staged pipeline; all smem addresses hoisted out of the k-loop.

__device__ __forceinline__ uint32_t f2tf32(float v) {
    uint32_t r;
    asm("cvt.rna.tf32.f32 %0, %1;" : "=r"(r) : "f"(v));
    return r;
}

__device__ __forceinline__ void mma_tf32(float* c, const uint32_t* a, const uint32_t* b) {
    asm volatile(
        "mma.sync.aligned.m16n8k8.row.col.f32.tf32.tf32.f32 "
        "{%0,%1,%2,%3}, {%4,%5,%6,%7}, {%8,%9}, {%0,%1,%2,%3};"
        : "+f"(c[0]), "+f"(c[1]), "+f"(c[2]), "+f"(c[3])
        : "r"(a[0]), "r"(a[1]), "r"(a[2]), "r"(a[3]),
          "r"(b[0]), "r"(b[1]));
}

__device__ __forceinline__ int permu(int lane, int block) {
    return (lane ^ (lane >> 2) ^ block) & 31;
}

__global__ void __launch_bounds__(256) k_gemm_tc(
    const float* __restrict__ Aext, int use_gh,
    const float* __restrict__ Wa, const float* __restrict__ Wb,
    const float* __restrict__ bias,
    int N, int dout)
{
    const float* A = use_gh ? (const float*)g_h : Aext;
    const int z = blockIdx.z;
    const float* W = z ? Wb : Wa;
    float* C = z ? g_hn : g_self;

    // sA: block (kc*8 + m16) * 32 lanes * 4 slots; slot = half*2 + khalf
    // sB: block (kc*16 + n8) * 32 lanes * 2 slots; slot = khalf
    __shared__ __align__(16) uint32_t sA[2048];
    __shared__ __align__(16) uint32_t sB[2048];

    const int tid  = threadIdx.x;
    const int lane = tid & 31;
    const int w    = tid >> 5;
    const int wr   = w >> 2;
    const int wc   = w & 3;
    const int rowBase = blockIdx.y * 128;
    const int colBase = blockIdx.x * 128;

    float acc[4][4][4];
#pragma unroll
    for (int mt = 0; mt < 4; ++mt)
#pragma unroll
        for (int nt = 0; nt < 4; ++nt)
#pragma unroll
            for (int s = 0; s < 4; ++s) acc[mt][nt][s] = 0.f;

    // ---- hoisted writer addressing ----
    // A: thread -> row ar, k-half akc (8 k's)
    const int ar    = tid >> 1;
    const int akc   = tid & 1;
    const int a_blk = akc * 8 + (ar >> 4);
    const int a_hf  = (ar >> 3) & 1;
    const int a_g   = ar & 7;
    const bool a_ok = (rowBase + ar) < N;
    const float* Ap = A + (size_t)(rowBase + ar) * KDIM + akc * 8;
    int wA[4];
#pragma unroll
    for (int j = 0; j < 4; ++j)
        wA[j] = a_blk * 128 + permu(a_g * 4 + j, a_blk) * 4 + 2 * a_hf;

    // B: thread -> k-rows br, br+8; 4 cols
    const int br  = tid >> 5;
    const int bc4 = tid & 31;
    int wB[2][4];
#pragma unroll
    for (int rb = 0; rb < 2; ++rb) {
        const int rk = br + rb * 8;
        const int kc = rk >> 3, kq = rk & 7;
        const int khalf = kq >> 2, q = kq & 3;
#pragma unroll
        for (int j = 0; j < 4; ++j) {
            const int n = bc4 * 4 + j;
            const int blk = kc * 16 + (n >> 3);
            wB[rb][j] = blk * 64 + permu((n & 7) * 4 + q, blk) * 2 + khalf;
        }
    }
    const float* Wp0 = W + (size_t)br * dout + colBase + bc4 * 4;
    const float* Wp1 = Wp0 + (size_t)8 * dout;

    // ---- hoisted reader addressing ----
    int rA[2][4], rB[2][4];
#pragma unroll
    for (int kc = 0; kc < 2; ++kc) {
#pragma unroll
        for (int mt = 0; mt < 4; ++mt) {
            const int blk = kc * 8 + wr * 4 + mt;
            rA[kc][mt] = blk * 128 + permu(lane, blk) * 4;
        }
#pragma unroll
        for (int nt = 0; nt < 4; ++nt) {
            const int blk = kc * 16 + wc * 4 + nt;
            rB[kc][nt] = blk * 64 + permu(lane, blk) * 2;
        }
    }

    // ---- pipelined main loop ----
    float4 av0 = make_float4(0.f, 0.f, 0.f, 0.f), av1 = av0;
    float4 bv0, bv1;
    if (a_ok) { av0 = *(const float4*)(Ap); av1 = *(const float4*)(Ap + 4); }
    bv0 = *(const float4*)(Wp0);
    bv1 = *(const float4*)(Wp1);

    for (int kt = 0; kt < KDIM; kt += 16) {
        // scatter staged tile
        {
            const float e0[4] = {av0.x, av0.y, av0.z, av0.w};
            const float e1[4] = {av1.x, av1.y, av1.z, av1.w};
#pragma unroll
            for (int j = 0; j < 4; ++j)
                *(uint2*)&sA[wA[j]] = make_uint2(f2tf32(e0[j]), f2tf32(e1[j]));
            const float f0[4] = {bv0.x, bv0.y, bv0.z, bv0.w};
            const float f1[4] = {bv1.x, bv1.y, bv1.z, bv1.w};
#pragma unroll
            for (int j = 0; j < 4; ++j) {
                sB[wB[0][j]] = f2tf32(f0[j]);
                sB[wB[1][j]] = f2tf32(f1[j]);
            }
        }
        __syncthreads();

        // prefetch next tile
        if (kt + 16 < KDIM) {
            if (a_ok) {
                av0 = *(const float4*)(Ap + kt + 16);
                av1 = *(const float4*)(Ap + kt + 20);
            }
            bv0 = *(const float4*)(Wp0 + (size_t)(kt + 16) * dout);
            bv1 = *(const float4*)(Wp1 + (size_t)(kt + 16) * dout);
        }

        // compute
#pragma unroll
        for (int kc = 0; kc < 2; ++kc) {
            uint32_t afr[4][4];
            uint32_t bfr[4][2];
#pragma unroll
            for (int mt = 0; mt < 4; ++mt) {
                const uint4 v = *(const uint4*)&sA[rA[kc][mt]];
                // slots: (h0,k0),(h0,k1),(h1,k0),(h1,k1) -> a0,a2,a1,a3
                afr[mt][0] = v.x; afr[mt][1] = v.z;
                afr[mt][2] = v.y; afr[mt][3] = v.w;
            }
#pragma unroll
            for (int nt = 0; nt < 4; ++nt) {
                const uint2 v = *(const uint2*)&sB[rB[kc][nt]];
                bfr[nt][0] = v.x; bfr[nt][1] = v.y;
            }
#pragma unroll
            for (int mt = 0; mt < 4; ++mt)
#pragma unroll
                for (int nt = 0; nt < 4; ++nt)
                    mma_tf32(acc[mt][nt], afr[mt], bfr[nt]);
        }
        __syncthreads();
    }

    // ---- epilogue ----
    const int g = lane >> 2, q = lane & 3;
#pragma unroll
    for (int nt = 0; nt < 4; ++nt) {
        const int col = colBase + wc * 32 + nt * 8 + 2 * q;
        float bx = 0.f, by = 0.f;
        if (z == 0) {
            const float2 bb = *(const float2*)&bias[col];
            bx = bb.x; by = bb.y;
        }
#pragma unroll
        for (int mt = 0; mt < 4; ++mt) {
            const int row = rowBase + wr * 64 + mt * 16 + g;
            if (row < N) {
                float2 o = make_float2(acc[mt][nt][0] + bx, acc[mt][nt][1] + by);
                *(float2*)&C[(size_t)row * dout + col] = o;
            }
            if (row + 8 < N) {
                float2 o = make_float2(acc[mt][nt][2] + bx, acc[mt][nt][3] + by);
                *(float2*)&C[(size_t)(row + 8) * dout + col] = o;
            }
        }
    }
}

// -------------------- fused aggregate + epilogue ---------------------------
// 64 threads/node, float4 per thread (256 cols). LN + ReLU -> g_h.

__global__ void __launch_bounds__(64) k_agg_ln(
    const float* __restrict__ deg, const float* __restrict__ g,
    const float* __restrict__ be)
{
    const int i = blockIdx.x;
    const int c = threadIdx.x;          // 0..63
    const float4* hn = (const float4*)g_hn;   // row stride 64
    const int s = g_off[i], e2 = g_off[i + 1];

    float4 acc = make_float4(0.f, 0.f, 0.f, 0.f);
    int e = s;
    for (; e + 8 <= e2; e += 8) {
        float4 v[8];
#pragma unroll
        for (int u = 0; u < 8; ++u)
            v[u] = hn[(size_t)g_csr[e + u] * 64 + c];
#pragma unroll
        for (int u = 0; u < 8; ++u) {
            acc.x += v[u].x; acc.y += v[u].y; acc.z += v[u].z; acc.w += v[u].w;
        }
    }
    for (; e < e2; ++e) {
        float4 v = hn[(size_t)g_csr[e] * 64 + c];
        acc.x += v.x; acc.y += v.y; acc.z += v.z; acc.w += v.w;
    }

    const float4 sf = ((const float4*)g_self)[(size_t)i * 64 + c];
    const float inv = 1.f / deg[i];
    float4 val;
    val.x = fmaf(acc.x, inv, sf.x);
    val.y = fmaf(acc.y, inv, sf.y);
    val.z = fmaf(acc.z, inv, sf.z);
    val.w = fmaf(acc.w, inv, sf.w);

    float sum = val.x + val.y + val.z + val.w;
    float sq  = val.x * val.x + val.y * val.y + val.z * val.z + val.w * val.w;
#pragma unroll
    for (int o = 16; o > 0; o >>= 1) {
        sum += __shfl_xor_sync(0xffffffffu, sum, o);
        sq  += __shfl_xor_sync(0xffffffffu, sq, o);
    }
    __shared__ float sa[2], sb[2];
    const int wid = c >> 5;
    if ((c & 31) == 0) { sa[wid] = sum; sb[wid] = sq; }
    __syncthreads();
    sum = sa[0] + sa[1];
    sq  = sb[0] + sb[1];

    const float mean = sum * (1.f / 256.f);
    const float var  = sq * (1.f / 256.f) - mean * mean;
    const float rstd = rsqrtf(var + 1e-5f);

    const float4 gg = ((const float4*)g)[c];
    const float4 bb = ((const float4*)be)[c];
    float4 o;
    o.x = fmaxf((val.x - mean) * rstd * gg.x + bb.x, 0.f);
    o.y = fmaxf((val.y - mean) * rstd * gg.y + bb.y, 0.f);
    o.z = fmaxf((val.z - mean) * rstd * gg.z + bb.z, 0.f);
    o.w = fmaxf((val.w - mean) * rstd * gg.w + bb.w, 0.f);
    ((float4*)g_h)[(size_t)i * 64 + c] = o;
}

// 32 threads/node, float4 (128 cols), no LN -> out.

__global__ void __launch_bounds__(32) k_agg_final(
    const float* __restrict__ deg, float* __restrict__ out)
{
    const int i = blockIdx.x;
    const int c = threadIdx.x;          // 0..31
    const float4* hn = (const float4*)g_hn;   // row stride 32
    const int s = g_off[i], e2 = g_off[i + 1];

    float4 acc = make_float4(0.f, 0.f, 0.f, 0.f);
    int e = s;
    for (; e + 8 <= e2; e += 8) {
        float4 v[8];
#pragma unroll
        for (int u = 0; u < 8; ++u)
            v[u] = hn[(size_t)g_csr[e + u] * 32 + c];
#pragma unroll
        for (int u = 0; u < 8; ++u) {
            acc.x += v[u].x; acc.y += v[u].y; acc.z += v[u].z; acc.w += v[u].w;
        }
    }
    for (; e < e2; ++e) {
        float4 v = hn[(size_t)g_csr[e] * 32 + c];
        acc.x += v.x; acc.y += v.y; acc.z += v.z; acc.w += v.w;
    }

    const float4 sf = ((const float4*)g_self)[(size_t)i * 32 + c];
    const float inv = 1.f / deg[i];
    float4 o;
    o.x = fmaf(acc.x, inv, sf.x);
    o.y = fmaf(acc.y, inv, sf.y);
    o.z = fmaf(acc.z, inv, sf.z);
    o.w = fmaf(acc.w, inv, sf.w);
    ((float4*)out)[(size_t)i * 32 + c] = o;
}

// ------------------------------- launcher ----------------------------------

extern "C" void kernel_launch(void* const* d_in, const int* in_sizes, int n_in,
                              void* d_out, int out_size)
{
    const float* feat   = (const float*)d_in[0];
    const int*   ei     = (const int*)  d_in[1];
    const float* in_deg = (const float*)d_in[2];
    const float* ws0 = (const float*)d_in[3];
    const float* wn0 = (const float*)d_in[4];
    const float* b0  = (const float*)d_in[5];
    const float* ws1 = (const float*)d_in[6];
    const float* wn1 = (const float*)d_in[7];
    const float* b1  = (const float*)d_in[8];
    const float* ws2 = (const float*)d_in[9];
    const float* wn2 = (const float*)d_in[10];
    const float* b2  = (const float*)d_in[11];
    const float* g0  = (const float*)d_in[12];
    const float* be0 = (const float*)d_in[13];
    const float* g1  = (const float*)d_in[14];
    const float* be1 = (const float*)d_in[15];

    const int N = in_sizes[0] / 256;   // 50000
    const int E = in_sizes[1] / 2;     // 800000
    const int* src = ei;
    const int* dst = ei + E;
    float* out = (float*)d_out;

    const int nbN = (N + 255) / 256;
    const int nbE = (E + 255) / 256;
    const int rowBlocks = (N + 127) / 128;

    // Launch order: layer-0 GEMM is launch #6 (ncu -s 5 -c 1 profiles it).
    k_zero<<<nbN, 256>>>(N);                                     // 1
    k_count<<<nbE, 256>>>(dst, E);                               // 2
    k_scan_chunk<<<nbN, 256>>>(N);                               // 3
    k_scan_top<<<1, 256>>>(nbN);                                 // 4
    k_scan_add<<<nbN, 256>>>(N);                                 // 5
    k_gemm_tc<<<dim3(2, rowBlocks, 2), 256>>>(feat, 0, ws0, wn0, b0, N, 256); // 6
    k_cursor<<<nbN, 256>>>(N);                                   // 7
    k_fill<<<nbE, 256>>>(src, dst, E);                           // 8
    k_agg_ln<<<N, 64>>>(in_deg, g0, be0);                        // 9

    k_gemm_tc<<<dim3(2, rowBlocks, 2), 256>>>(feat, 1, ws1, wn1, b1, N, 256);
    k_agg_ln<<<N, 64>>>(in_deg, g1, be1);

    k_gemm_tc<<<dim3(1, rowBlocks, 2), 256>>>(feat, 1, ws2, wn2, b2, N, 128);
    k_agg_final<<<N, 32>>>(in_deg, out);
}